// round 5
// baseline (speedup 1.0000x reference)
#include <cuda_runtime.h>

// ---------------------------------------------------------------------------
// MS-SSIM, 4 levels, 11-tap Gaussian (sigma=1.5), VALID padding.
// X, Y: [16, 3, 512, 512] fp32. Output: 16 fp32 (1 - ms_ssim per batch).
//
// R5: 3 launches.
//  (1) pool_all_kernel: hierarchical 2x2/4x4/8x8 average -> pyramid levels
//      1..3 in one pass over X,Y; block 0 zeroes accumulators.
//  (2) ssim_all_kernel: ALL four SSIM levels in one launch (heterogeneous
//      blocks by blockIdx range, 4 template instantiations). Register-ring
//      vertical pass, packed fma.rn.f32x2 math.
//  (3) finalize.
// ---------------------------------------------------------------------------

#define KW 11
#define NB 16
#define NC 3

__device__ double g_acc[4 * NB];
__device__ float g_X1[NB * NC * 256 * 256];
__device__ float g_Y1[NB * NC * 256 * 256];
__device__ float g_X2[NB * NC * 128 * 128];
__device__ float g_Y2[NB * NC * 128 * 128];
__device__ float g_X3[NB * NC * 64 * 64];
__device__ float g_Y3[NB * NC * 64 * 64];

typedef unsigned long long ull;

__device__ __forceinline__ ull pk2(float lo, float hi) {
    ull r; asm("mov.b64 %0,{%1,%2};" : "=l"(r) : "f"(lo), "f"(hi)); return r;
}
__device__ __forceinline__ void up2(ull v, float& lo, float& hi) {
    asm("mov.b64 {%0,%1},%2;" : "=f"(lo), "=f"(hi) : "l"(v));
}
__device__ __forceinline__ ull fma2(ull a, ull b, ull c) {
    ull d; asm("fma.rn.f32x2 %0,%1,%2,%3;" : "=l"(d) : "l"(a), "l"(b), "l"(c));
    return d;
}
__device__ __forceinline__ ull mul2(ull a, ull b) {
    ull d; asm("mul.rn.f32x2 %0,%1,%2;" : "=l"(d) : "l"(a), "l"(b));
    return d;
}

// ---------------------------------------------------------------------------
// Pool kernel: each block handles a 32x32 patch of one plane; emits 16x16 of
// level-1, 8x8 of level-2, 4x4 of level-3. Grid: 48 planes * 256 patches.
// ---------------------------------------------------------------------------
__global__ __launch_bounds__(256) void pool_all_kernel(
    const float* __restrict__ X, const float* __restrict__ Y)
{
    if (blockIdx.x == 0 && threadIdx.x < 4 * NB) g_acc[threadIdx.x] = 0.0;

    __shared__ float2 s1[16][17];
    __shared__ float2 s2[8][9];

    const int plane = blockIdx.x >> 8;        // 0..47
    const int patch = blockIdx.x & 255;
    const int px = patch & 15, py = patch >> 4;
    const int tid = threadIdx.x;
    const int tx = tid & 15, ty = tid >> 4;

    const float* __restrict__ Xp = X + (size_t)plane * 512 * 512;
    const float* __restrict__ Yp = Y + (size_t)plane * 512 * 512;

    const int gy = py * 32 + 2 * ty;
    const int gx = px * 32 + 2 * tx;
    const int o0 = gy * 512 + gx;

    float2 xa = *(const float2*)(Xp + o0);
    float2 xb = *(const float2*)(Xp + o0 + 512);
    float2 ya = *(const float2*)(Yp + o0);
    float2 yb = *(const float2*)(Yp + o0 + 512);
    float xv = 0.25f * ((xa.x + xa.y) + (xb.x + xb.y));
    float yv = 0.25f * ((ya.x + ya.y) + (yb.x + yb.y));

    // level 1 write (256x256 per plane)
    g_X1[(size_t)plane * 256 * 256 + (py * 16 + ty) * 256 + (px * 16 + tx)] = xv;
    g_Y1[(size_t)plane * 256 * 256 + (py * 16 + ty) * 256 + (px * 16 + tx)] = yv;
    s1[ty][tx] = make_float2(xv, yv);
    __syncthreads();

    if (tid < 64) {
        int t2x = tid & 7, t2y = tid >> 3;
        float2 a = s1[2 * t2y][2 * t2x];
        float2 b = s1[2 * t2y][2 * t2x + 1];
        float2 c = s1[2 * t2y + 1][2 * t2x];
        float2 d = s1[2 * t2y + 1][2 * t2x + 1];
        float x2 = 0.25f * ((a.x + b.x) + (c.x + d.x));
        float y2 = 0.25f * ((a.y + b.y) + (c.y + d.y));
        g_X2[(size_t)plane * 128 * 128 + (py * 8 + t2y) * 128 + (px * 8 + t2x)] = x2;
        g_Y2[(size_t)plane * 128 * 128 + (py * 8 + t2y) * 128 + (px * 8 + t2x)] = y2;
        s2[t2y][t2x] = make_float2(x2, y2);
    }
    __syncthreads();

    if (tid < 16) {
        int t3x = tid & 3, t3y = tid >> 2;
        float2 a = s2[2 * t3y][2 * t3x];
        float2 b = s2[2 * t3y][2 * t3x + 1];
        float2 c = s2[2 * t3y + 1][2 * t3x];
        float2 d = s2[2 * t3y + 1][2 * t3x + 1];
        float x3 = 0.25f * ((a.x + b.x) + (c.x + d.x));
        float y3 = 0.25f * ((a.y + b.y) + (c.y + d.y));
        g_X3[(size_t)plane * 64 * 64 + (py * 4 + t3y) * 64 + (px * 4 + t3x)] = x3;
        g_Y3[(size_t)plane * 64 * 64 + (py * 4 + t3y) * 64 + (px * 4 + t3x)] = y3;
    }
}

// ---------------------------------------------------------------------------
// Per-tile SSIM device function (register ring, packed f32x2). Block = 128
// threads; for TW_=64 the upper 64 threads only help with loads/reduction.
// ---------------------------------------------------------------------------
template<int TW_, int TH_, bool LAST>
__device__ __forceinline__ void ssim_tile(
    const float* __restrict__ Xb, const float* __restrict__ Yb,
    int H, int outH, int tilesX, int tilesY, int level, int idx,
    float2* __restrict__ sxy, float* __restrict__ red)
{
    constexpr int IH_  = TH_ + KW - 1;
    constexpr int IW_  = TW_ + KW - 1;
    constexpr int IWP_ = TW_ + 12;

    const int ntiles = tilesX * tilesY;
    const int tile   = idx % ntiles;
    const int plane  = idx / ntiles;       // b*NC + c
    const int b      = plane / NC;
    const int tx = tile % tilesX;
    const int ty = tile / tilesX;
    const int ix0 = tx * TW_;
    const int iy0 = ty * TH_;
    const int tid = threadIdx.x;
    const int W = H, outW = outH;

    const size_t poff = (size_t)plane * H * W;
    const float* __restrict__ Xi = Xb + poff;
    const float* __restrict__ Yi = Yb + poff;

    #pragma unroll 4
    for (int i = tid; i < IH_ * IW_; i += 128) {
        int r  = i / IW_;
        int cc = i - r * IW_;
        int gy = min(iy0 + r,  H - 1);
        int gx = min(ix0 + cc, W - 1);
        int gi = gy * W + gx;
        sxy[r * IWP_ + cc] = make_float2(Xi[gi], Yi[gi]);
    }
    __syncthreads();

    const float G[KW] = {
        0.00102838f, 0.00759875f, 0.03600077f, 0.10936069f, 0.21300553f,
        0.26601174f,
        0.21300553f, 0.10936069f, 0.03600077f, 0.00759875f, 0.00102838f
    };
    const float C1 = 1e-4f;
    const float C2 = 9e-4f;

    float local = 0.f;
    const int lx = tid;
    if (lx < TW_) {
        ull   r01[KW];
        ull   r23[KW];
        float r4[KW];
        const int ox = ix0 + lx;
        const bool colOK = (ox < outW);

        #pragma unroll
        for (int r = 0; r < IH_; r++) {
            const ull* __restrict__ row =
                reinterpret_cast<const ull*>(&sxy[r * IWP_ + lx]);
            ull s01, s23; float s4;
            {
                ull v = row[0];
                ull gg = pk2(G[0], G[0]);
                s01 = mul2(gg, v);
                ull t = mul2(gg, v);
                s23 = mul2(t, v);
                float xv, yv, tl, th;
                up2(v, xv, yv); up2(t, tl, th);
                s4 = tl * yv;
                (void)xv; (void)th;
            }
            #pragma unroll
            for (int k = 1; k < KW; k++) {
                ull v = row[k];
                ull gg = pk2(G[k], G[k]);
                s01 = fma2(gg, v, s01);
                ull t = mul2(gg, v);
                s23 = fma2(t, v, s23);
                float xv, yv, tl, th;
                up2(v, xv, yv); up2(t, tl, th);
                s4 = fmaf(tl, yv, s4);
                (void)xv; (void)th;
            }
            r01[r % KW] = s01;
            r23[r % KW] = s23;
            r4[r % KW]  = s4;

            if (r >= KW - 1) {
                const int orow = r - (KW - 1);
                ull m01, m23; float m4;
                {
                    int id0 = orow % KW;
                    ull gg = pk2(G[0], G[0]);
                    m01 = mul2(gg, r01[id0]);
                    m23 = mul2(gg, r23[id0]);
                    m4  = G[0] * r4[id0];
                }
                #pragma unroll
                for (int k = 1; k < KW; k++) {
                    int id = (orow + k) % KW;
                    ull gg = pk2(G[k], G[k]);
                    m01 = fma2(gg, r01[id], m01);
                    m23 = fma2(gg, r23[id], m23);
                    m4  = fmaf(G[k], r4[id], m4);
                }
                int oy = iy0 + orow;
                if (colOK && oy < outH) {
                    float mu1, mu2, xx, yy;
                    up2(m01, mu1, mu2);
                    up2(m23, xx, yy);
                    float s1q = xx - mu1 * mu1;
                    float s2q = yy - mu2 * mu2;
                    float s12 = m4 - mu1 * mu2;
                    float cs = __fdividef(2.f * s12 + C2, s1q + s2q + C2);
                    cs = fmaxf(cs, 0.f);
                    if (LAST) {
                        float lum = __fdividef(2.f * mu1 * mu2 + C1,
                                               mu1 * mu1 + mu2 * mu2 + C1);
                        local = fmaf(lum, cs, local);
                    } else {
                        local += cs;
                    }
                }
            }
        }
    }

    #pragma unroll
    for (int s = 16; s > 0; s >>= 1)
        local += __shfl_down_sync(0xffffffffu, local, s);
    if ((tid & 31) == 0) red[tid >> 5] = local;
    __syncthreads();
    if (tid == 0) {
        float t = red[0] + red[1] + red[2] + red[3];
        atomicAdd(&g_acc[level * NB + b], (double)t);
    }
}

// Block-count constants (compile-time; shapes are fixed by the problem).
#define N0 (4 * 16 * NC * NB)   // L0: 128x32 tiles over 502x502 -> 3072
#define N1 (2 * 8  * NC * NB)   // L1: 128x32 over 246x246      -> 768
#define N2 (1 * 8  * NC * NB)   // L2: 128x16 over 118x118      -> 384
#define N3 (1 * 4  * NC * NB)   // L3: 64x16  over 54x54        -> 192

// Dynamic smem: max tile = 42 rows x 140 float2 = 47040 B, + 16 B reduction.
#define SMEM_BYTES (42 * 140 * 8 + 16)

__global__ __launch_bounds__(128) void ssim_all_kernel(
    const float* __restrict__ X, const float* __restrict__ Y)
{
    extern __shared__ char smem_raw[];
    float2* sxy = (float2*)smem_raw;
    float*  red = (float*)(smem_raw + 42 * 140 * 8);

    int bx = blockIdx.x;
    if (bx < N0) {
        ssim_tile<128, 32, false>(X, Y, 512, 502, 4, 16, 0, bx, sxy, red);
    } else if (bx < N0 + N1) {
        ssim_tile<128, 32, false>(g_X1, g_Y1, 256, 246, 2, 8, 1, bx - N0,
                                  sxy, red);
    } else if (bx < N0 + N1 + N2) {
        ssim_tile<128, 16, false>(g_X2, g_Y2, 128, 118, 1, 8, 2,
                                  bx - N0 - N1, sxy, red);
    } else {
        ssim_tile<64, 16, true>(g_X3, g_Y3, 64, 54, 1, 4, 3,
                                bx - N0 - N1 - N2, sxy, red);
    }
}

__global__ void finalize_kernel(float* __restrict__ out) {
    int b = threadIdx.x;
    if (b >= NB) return;
    const double counts[4] = {
        3.0 * 502.0 * 502.0,
        3.0 * 246.0 * 246.0,
        3.0 * 118.0 * 118.0,
        3.0 * 54.0  * 54.0
    };
    const double wraw[4] = {0.0448, 0.2856, 0.3001, 0.2363};
    const double wsum = 0.0448 + 0.2856 + 0.3001 + 0.2363;
    double s = 0.0;
    #pragma unroll
    for (int l = 0; l < 4; l++) {
        double v = g_acc[l * NB + b] / counts[l];
        v = v > 1e-8 ? v : 1e-8;
        s += (wraw[l] / wsum) * log(v);
    }
    out[b] = (float)(1.0 - exp(s));
}

extern "C" void kernel_launch(void* const* d_in, const int* in_sizes, int n_in,
                              void* d_out, int out_size)
{
    const float* X = (const float*)d_in[0];
    const float* Y = (const float*)d_in[1];
    float* out = (float*)d_out;
    (void)in_sizes; (void)n_in; (void)out_size;

    // (1) pools (levels 1..3) + accumulator zeroing
    pool_all_kernel<<<NB * NC * 256, 256>>>(X, Y);

    // (2) all four SSIM levels in one launch
    ssim_all_kernel<<<N0 + N1 + N2 + N3, 128, SMEM_BYTES>>>(X, Y);

    // (3) finalize
    finalize_kernel<<<1, 32>>>(out);
}